// round 13
// baseline (speedup 1.0000x reference)
#include <cuda_runtime.h>
#include <cstdint>

// YOLO loss R13: R12 (best) with perfect work balance.
// 6272 tiles / 448 blocks = exactly 14 tiles per block -> no straggler tail.
// 2-stage cp.async ring, 30KB tiles, 128 threads, all 4 warps compute
// (warp w -> (w&1?odd:even) cell of pair (w>>1)*32+lane).
// Deterministic reduction (fixed tile map, fixed-order final sum).

#define NCELLS  (16384 * 7 * 7)    // 802816
#define TILE_C  128                // cells per tile
#define THREADS 128
#define TV4     (TILE_C * 30 / 4)  // 960 float4 per tensor per tile
#define STAGE_V4 (2 * TV4)         // 1920 float4 per stage (pred + tgt)
#define NSTAGES 2
#define NTILES  (NCELLS / TILE_C)  // 6272 exact
#define GRID    448                // 6272 / 448 = 14 tiles per block, exact
#define SMEM_BYTES (NSTAGES * STAGE_V4 * 16)  // 61440

__device__ float    g_partial[2048];
__device__ unsigned g_count = 0;

__device__ __forceinline__ void cp_async16(void* smem_dst, const void* gmem_src) {
    unsigned saddr = (unsigned)__cvta_generic_to_shared(smem_dst);
    asm volatile("cp.async.cg.shared.global [%0], [%1], 16;\n"
                 :: "r"(saddr), "l"(gmem_src) : "memory");
}
__device__ __forceinline__ void cp_commit() {
    asm volatile("cp.async.commit_group;\n" ::: "memory");
}
template <int N>
__device__ __forceinline__ void cp_wait() {
    asm volatile("cp.async.wait_group %0;\n" :: "n"(N) : "memory");
}

__device__ __forceinline__ float iou_f(float x1, float y1, float w1, float h1,
                                       float x2, float y2, float w2, float h2) {
    float xl = fmaxf(x1 - w1 * 0.5f, x2 - w2 * 0.5f);
    float yt = fmaxf(y1 - h1 * 0.5f, y2 - h2 * 0.5f);
    float xr = fminf(x1 + w1 * 0.5f, x2 + w2 * 0.5f);
    float yb = fminf(y1 + h1 * 0.5f, y2 + h2 * 0.5f);
    bool valid = (xr >= xl) && (yb >= yt);
    float inter = (xr - xl) * (yb - yt);
    float uni = w1 * h1 + w2 * h2 - inter;
    float safe = (uni == 0.0f) ? 1.0f : uni;
    return valid ? (inter / safe) : 0.0f;
}

__device__ __forceinline__ float cell_loss(float t0, float t1, float t2, float t3, float t4,
                                           float p0, float p1, float p2, float p3, float p4,
                                           float p5, float p6, float p7, float p8, float p9,
                                           float cls) {
    float obj   = (t4 > 0.0f)  ? 1.0f : 0.0f;
    float noobj = (t4 == 0.0f) ? 1.0f : 0.0f;

    float dno = t4 - p4;
    float conf_noobj = noobj * dno * dno;

    float iou1 = iou_f(t0, t1, t2, t3, p0, p1, p2, p3);
    float iou2 = iou_f(t0, t1, t2, t3, p5, p6, p7, p8);
    float resp1 = (iou1 > iou2) ? 1.0f : 0.0f;
    float m1 = obj * resp1;
    float m2 = obj * (1.0f - resp1);

    float d1 = iou1 - p4;
    float d2 = iou2 - p9;
    float conf_obj = m1 * d1 * d1 + m2 * d2 * d2;

    float dx1 = t0 - p0, dy1 = t1 - p1;
    float dx2 = t0 - p5, dy2 = t1 - p6;
    float xy = m1 * (dx1 * dx1 + dy1 * dy1) + m2 * (dx2 * dx2 + dy2 * dy2);

    float dw1 = t2 - p2, dh1 = t3 - p3;
    float dw2 = t2 - p7, dh2 = t3 - p8;
    float wh = m1 * (dw1 * dw1 + dh1 * dh1) + m2 * (dw2 * dw2 + dh2 * dh2);

    return 5.0f * (xy + wh) + conf_obj + 0.5f * conf_noobj + obj * cls;
}

// Even cell of a pair (slots 0..7): static mapping.
__device__ __forceinline__ float even_cell(const float4* __restrict__ SP,
                                           const float4* __restrict__ ST) {
    float cls = 0.0f;
#pragma unroll
    for (int j = 3; j <= 6; j++) {
        float4 a = ST[j], b = SP[j];
        float d0 = a.x - b.x, d1 = a.y - b.y, d2 = a.z - b.z, d3 = a.w - b.w;
        cls += d0 * d0 + d1 * d1 + d2 * d2 + d3 * d3;
    }
    float4 P2 = SP[2], T2 = ST[2];
    { float d0 = T2.z - P2.z, d1 = T2.w - P2.w; cls += d0 * d0 + d1 * d1; }
    float4 P7 = SP[7], T7 = ST[7];
    { float d0 = T7.x - P7.x, d1 = T7.y - P7.y; cls += d0 * d0 + d1 * d1; }

    float4 P0 = SP[0], P1 = SP[1], T0 = ST[0], T1 = ST[1];
    return cell_loss(T0.x, T0.y, T0.z, T0.w, T1.x,
                     P0.x, P0.y, P0.z, P0.w, P1.x,
                     P1.y, P1.z, P1.w, P2.x, P2.y, cls);
}

// Odd cell of a pair (slots 7..14): static mapping.
__device__ __forceinline__ float odd_cell(const float4* __restrict__ SP,
                                          const float4* __restrict__ ST) {
    float cls = 0.0f;
#pragma unroll
    for (int j = 10; j <= 14; j++) {
        float4 a = ST[j], b = SP[j];
        float d0 = a.x - b.x, d1 = a.y - b.y, d2 = a.z - b.z, d3 = a.w - b.w;
        cls += d0 * d0 + d1 * d1 + d2 * d2 + d3 * d3;
    }
    float4 P7 = SP[7], P8 = SP[8], P9 = SP[9];
    float4 T7 = ST[7], T8 = ST[8];
    return cell_loss(T7.z, T7.w, T8.x, T8.y, T8.z,
                     P7.z, P7.w, P8.x, P8.y, P8.z,
                     P8.w, P9.x, P9.y, P9.z, P9.w, cls);
}

__device__ __forceinline__ void prefetch_tile(float4* sbuf, int s,
                                              const float4* __restrict__ gp,
                                              const float4* __restrict__ gt,
                                              int tile, int tid) {
    float4* dst = sbuf + s * STAGE_V4;
    const float4* srcp = gp + (size_t)tile * TV4;
    const float4* srct = gt + (size_t)tile * TV4;
#pragma unroll
    for (int k = 0; k < 15; k++) {
        int i = k * THREADS + tid;               // 0..1919
        const float4* src = (i < TV4) ? (srcp + i) : (srct + (i - TV4));
        cp_async16(dst + i, src);
    }
}

__global__ void __launch_bounds__(THREADS)
yolo_fused_kernel(const float* __restrict__ pred,
                  const float* __restrict__ tgt,
                  float* __restrict__ out) {
    extern __shared__ float4 sbuf[];       // 2 stages x 1920 float4
    __shared__ float swarp[THREADS / 32];
    __shared__ int   s_isLast;

    const int tid  = threadIdx.x;
    const int lane = tid & 31;
    const int wid  = tid >> 5;
    const float4* gp = reinterpret_cast<const float4*>(pred);
    const float4* gt = reinterpret_cast<const float4*>(tgt);

    float loss = 0.0f;

    int t = blockIdx.x;
    int stage = 0;
    prefetch_tile(sbuf, 0, gp, gt, t, tid);
    cp_commit();

    // exactly 14 iterations per block (6272 / 448), perfectly balanced
#pragma unroll 1
    while (t < NTILES) {
        int tn = t + GRID;
        if (tn < NTILES) {
            prefetch_tile(sbuf, stage ^ 1, gp, gt, tn, tid);
            cp_commit();
            cp_wait<1>();            // current tile's group has landed
        } else {
            cp_wait<0>();
        }
        __syncthreads();

        {
            // warp w: (w&1 ? odd : even) cell of pair (w>>1)*32 + lane.
            int pair = ((wid >> 1) << 5) + lane;
            const float4* SP = sbuf + stage * STAGE_V4 + pair * 15;
            const float4* ST = SP + TV4;
            loss += (wid & 1) ? odd_cell(SP, ST) : even_cell(SP, ST);
        }
        __syncthreads();             // all reads done before this stage refills
        stage ^= 1;
        t = tn;
    }

    // ---- block reduce (deterministic) ----
#pragma unroll
    for (int off = 16; off > 0; off >>= 1)
        loss += __shfl_down_sync(0xFFFFFFFFu, loss, off);

    if (lane == 0) swarp[wid] = loss;
    __syncthreads();

    if (tid == 0) {
        g_partial[blockIdx.x] = swarp[0] + swarp[1] + swarp[2] + swarp[3];
        __threadfence();
        unsigned v = atomicAdd(&g_count, 1u);
        s_isLast = (v == (unsigned)(gridDim.x - 1)) ? 1 : 0;
    }
    __syncthreads();

    // ---- last block: deterministic final reduction ----
    if (s_isLast) {
        __shared__ double sd[THREADS];
        double acc = 0.0;
        for (int i = tid; i < GRID; i += THREADS)
            acc += (double)g_partial[i];
        sd[tid] = acc;
        __syncthreads();
#pragma unroll
        for (int stride = THREADS / 2; stride > 0; stride >>= 1) {
            if (tid < stride) sd[tid] += sd[tid + stride];
            __syncthreads();
        }
        if (tid == 0) {
            out[0] = (float)(sd[0] / 16384.0);
            g_count = 0;   // reset for next graph replay
        }
    }
}

extern "C" void kernel_launch(void* const* d_in, const int* in_sizes, int n_in,
                              void* d_out, int out_size) {
    const float* y  = (const float*)d_in[0];
    const float* gt = (const float*)d_in[1];
    float* out = (float*)d_out;

    static int attr_done = 0;
    if (!attr_done) {
        cudaFuncSetAttribute(yolo_fused_kernel,
                             cudaFuncAttributeMaxDynamicSharedMemorySize, SMEM_BYTES);
        attr_done = 1;
    }

    yolo_fused_kernel<<<GRID, THREADS, SMEM_BYTES>>>(y, gt, out);
}

// round 14
// speedup vs baseline: 1.0616x; 1.0616x over previous
#include <cuda_runtime.h>
#include <cstdint>

// YOLO loss FINAL (= R12, measured best 36.9us / DRAM 68.6%).
// 2-stage cp.async ring, 30KB tiles, 3 blocks/SM (GRID = 152*3 = 456 so SM
// load is balanced; per-block 13-vs-14-tile remainder is absorbed by
// co-resident blocks). 128 threads, all 4 warps compute: warp w handles the
// (w&1?odd:even) cell of pair (w>>1)*32+lane — fully static channel mapping,
// conflict-free LDS at 60-float pair stride.
// Deterministic: fixed tile->block map, fixed-order final reduction.

#define NCELLS  (16384 * 7 * 7)    // 802816
#define TILE_C  128                // cells per tile
#define THREADS 128
#define TV4     (TILE_C * 30 / 4)  // 960 float4 per tensor per tile
#define STAGE_V4 (2 * TV4)         // 1920 float4 per stage (pred + tgt)
#define NSTAGES 2
#define NTILES  (NCELLS / TILE_C)  // 6272 exact
#define GRID    456                // 152 SMs * 3 blocks
#define SMEM_BYTES (NSTAGES * STAGE_V4 * 16)  // 61440

__device__ float    g_partial[2048];
__device__ unsigned g_count = 0;

__device__ __forceinline__ void cp_async16(void* smem_dst, const void* gmem_src) {
    unsigned saddr = (unsigned)__cvta_generic_to_shared(smem_dst);
    asm volatile("cp.async.cg.shared.global [%0], [%1], 16;\n"
                 :: "r"(saddr), "l"(gmem_src) : "memory");
}
__device__ __forceinline__ void cp_commit() {
    asm volatile("cp.async.commit_group;\n" ::: "memory");
}
template <int N>
__device__ __forceinline__ void cp_wait() {
    asm volatile("cp.async.wait_group %0;\n" :: "n"(N) : "memory");
}

__device__ __forceinline__ float iou_f(float x1, float y1, float w1, float h1,
                                       float x2, float y2, float w2, float h2) {
    float xl = fmaxf(x1 - w1 * 0.5f, x2 - w2 * 0.5f);
    float yt = fmaxf(y1 - h1 * 0.5f, y2 - h2 * 0.5f);
    float xr = fminf(x1 + w1 * 0.5f, x2 + w2 * 0.5f);
    float yb = fminf(y1 + h1 * 0.5f, y2 + h2 * 0.5f);
    bool valid = (xr >= xl) && (yb >= yt);
    float inter = (xr - xl) * (yb - yt);
    float uni = w1 * h1 + w2 * h2 - inter;
    float safe = (uni == 0.0f) ? 1.0f : uni;
    return valid ? (inter / safe) : 0.0f;
}

__device__ __forceinline__ float cell_loss(float t0, float t1, float t2, float t3, float t4,
                                           float p0, float p1, float p2, float p3, float p4,
                                           float p5, float p6, float p7, float p8, float p9,
                                           float cls) {
    float obj   = (t4 > 0.0f)  ? 1.0f : 0.0f;
    float noobj = (t4 == 0.0f) ? 1.0f : 0.0f;

    float dno = t4 - p4;
    float conf_noobj = noobj * dno * dno;

    float iou1 = iou_f(t0, t1, t2, t3, p0, p1, p2, p3);
    float iou2 = iou_f(t0, t1, t2, t3, p5, p6, p7, p8);
    float resp1 = (iou1 > iou2) ? 1.0f : 0.0f;
    float m1 = obj * resp1;
    float m2 = obj * (1.0f - resp1);

    float d1 = iou1 - p4;
    float d2 = iou2 - p9;
    float conf_obj = m1 * d1 * d1 + m2 * d2 * d2;

    float dx1 = t0 - p0, dy1 = t1 - p1;
    float dx2 = t0 - p5, dy2 = t1 - p6;
    float xy = m1 * (dx1 * dx1 + dy1 * dy1) + m2 * (dx2 * dx2 + dy2 * dy2);

    float dw1 = t2 - p2, dh1 = t3 - p3;
    float dw2 = t2 - p7, dh2 = t3 - p8;
    float wh = m1 * (dw1 * dw1 + dh1 * dh1) + m2 * (dw2 * dw2 + dh2 * dh2);

    return 5.0f * (xy + wh) + conf_obj + 0.5f * conf_noobj + obj * cls;
}

// Even cell of a pair (slots 0..7): static mapping.
__device__ __forceinline__ float even_cell(const float4* __restrict__ SP,
                                           const float4* __restrict__ ST) {
    float cls = 0.0f;
#pragma unroll
    for (int j = 3; j <= 6; j++) {
        float4 a = ST[j], b = SP[j];
        float d0 = a.x - b.x, d1 = a.y - b.y, d2 = a.z - b.z, d3 = a.w - b.w;
        cls += d0 * d0 + d1 * d1 + d2 * d2 + d3 * d3;
    }
    float4 P2 = SP[2], T2 = ST[2];
    { float d0 = T2.z - P2.z, d1 = T2.w - P2.w; cls += d0 * d0 + d1 * d1; }
    float4 P7 = SP[7], T7 = ST[7];
    { float d0 = T7.x - P7.x, d1 = T7.y - P7.y; cls += d0 * d0 + d1 * d1; }

    float4 P0 = SP[0], P1 = SP[1], T0 = ST[0], T1 = ST[1];
    return cell_loss(T0.x, T0.y, T0.z, T0.w, T1.x,
                     P0.x, P0.y, P0.z, P0.w, P1.x,
                     P1.y, P1.z, P1.w, P2.x, P2.y, cls);
}

// Odd cell of a pair (slots 7..14): static mapping.
__device__ __forceinline__ float odd_cell(const float4* __restrict__ SP,
                                          const float4* __restrict__ ST) {
    float cls = 0.0f;
#pragma unroll
    for (int j = 10; j <= 14; j++) {
        float4 a = ST[j], b = SP[j];
        float d0 = a.x - b.x, d1 = a.y - b.y, d2 = a.z - b.z, d3 = a.w - b.w;
        cls += d0 * d0 + d1 * d1 + d2 * d2 + d3 * d3;
    }
    float4 P7 = SP[7], P8 = SP[8], P9 = SP[9];
    float4 T7 = ST[7], T8 = ST[8];
    return cell_loss(T7.z, T7.w, T8.x, T8.y, T8.z,
                     P7.z, P7.w, P8.x, P8.y, P8.z,
                     P8.w, P9.x, P9.y, P9.z, P9.w, cls);
}

__device__ __forceinline__ void prefetch_tile(float4* sbuf, int s,
                                              const float4* __restrict__ gp,
                                              const float4* __restrict__ gt,
                                              int tile, int tid) {
    float4* dst = sbuf + s * STAGE_V4;
    const float4* srcp = gp + (size_t)tile * TV4;
    const float4* srct = gt + (size_t)tile * TV4;
#pragma unroll
    for (int k = 0; k < 15; k++) {
        int i = k * THREADS + tid;               // 0..1919
        const float4* src = (i < TV4) ? (srcp + i) : (srct + (i - TV4));
        cp_async16(dst + i, src);
    }
}

__global__ void __launch_bounds__(THREADS)
yolo_fused_kernel(const float* __restrict__ pred,
                  const float* __restrict__ tgt,
                  float* __restrict__ out) {
    extern __shared__ float4 sbuf[];       // 2 stages x 1920 float4
    __shared__ float swarp[THREADS / 32];
    __shared__ int   s_isLast;

    const int tid  = threadIdx.x;
    const int lane = tid & 31;
    const int wid  = tid >> 5;
    const float4* gp = reinterpret_cast<const float4*>(pred);
    const float4* gt = reinterpret_cast<const float4*>(tgt);

    float loss = 0.0f;

    int t = blockIdx.x;
    int stage = 0;
    if (t < NTILES) prefetch_tile(sbuf, 0, gp, gt, t, tid);
    cp_commit();

    while (t < NTILES) {
        int tn = t + GRID;
        if (tn < NTILES) {
            prefetch_tile(sbuf, stage ^ 1, gp, gt, tn, tid);
            cp_commit();
            cp_wait<1>();            // current tile's group has landed
        } else {
            cp_wait<0>();
        }
        __syncthreads();

        {
            // warp w: (w&1 ? odd : even) cell of pair (w>>1)*32 + lane.
            int pair = ((wid >> 1) << 5) + lane;
            const float4* SP = sbuf + stage * STAGE_V4 + pair * 15;
            const float4* ST = SP + TV4;
            loss += (wid & 1) ? odd_cell(SP, ST) : even_cell(SP, ST);
        }
        __syncthreads();             // all reads done before this stage refills
        stage ^= 1;
        t = tn;
    }

    // ---- block reduce (deterministic) ----
#pragma unroll
    for (int off = 16; off > 0; off >>= 1)
        loss += __shfl_down_sync(0xFFFFFFFFu, loss, off);

    if (lane == 0) swarp[wid] = loss;
    __syncthreads();

    if (tid == 0) {
        g_partial[blockIdx.x] = swarp[0] + swarp[1] + swarp[2] + swarp[3];
        __threadfence();
        unsigned v = atomicAdd(&g_count, 1u);
        s_isLast = (v == (unsigned)(gridDim.x - 1)) ? 1 : 0;
    }
    __syncthreads();

    // ---- last block: deterministic final reduction ----
    if (s_isLast) {
        __shared__ double sd[THREADS];
        double acc = 0.0;
        for (int i = tid; i < GRID; i += THREADS)
            acc += (double)g_partial[i];
        sd[tid] = acc;
        __syncthreads();
#pragma unroll
        for (int stride = THREADS / 2; stride > 0; stride >>= 1) {
            if (tid < stride) sd[tid] += sd[tid + stride];
            __syncthreads();
        }
        if (tid == 0) {
            out[0] = (float)(sd[0] / 16384.0);
            g_count = 0;   // reset for next graph replay
        }
    }
}

extern "C" void kernel_launch(void* const* d_in, const int* in_sizes, int n_in,
                              void* d_out, int out_size) {
    const float* y  = (const float*)d_in[0];
    const float* gt = (const float*)d_in[1];
    float* out = (float*)d_out;

    static int attr_done = 0;
    if (!attr_done) {
        cudaFuncSetAttribute(yolo_fused_kernel,
                             cudaFuncAttributeMaxDynamicSharedMemorySize, SMEM_BYTES);
        attr_done = 1;
    }

    yolo_fused_kernel<<<GRID, THREADS, SMEM_BYTES>>>(y, gt, out);
}

// round 16
// speedup vs baseline: 1.1232x; 1.0580x over previous
#include <cuda_runtime.h>
#include <cstdint>

// YOLO loss R15: R12 winning shape (2-stage x 30KB ring, 3 blocks/SM,
// lockstep, all-warp even/odd static-pair compute) with staging switched
// from 15 per-thread cp.async to 2 TMA bulk copies issued by an elected
// thread + per-stage full-mbarrier parity waits. Removes ~all staging
// issue/address-math from the 4 compute warps.
// Deterministic: fixed tile map, fixed-order final reduction.

#define NCELLS  (16384 * 7 * 7)    // 802816
#define TILE_C  128                // cells per tile
#define THREADS 128
#define TV4     (TILE_C * 30 / 4)  // 960 float4 per tensor per tile
#define STAGE_V4 (2 * TV4)         // 1920 float4 per stage (pred + tgt)
#define TENSOR_BYTES (TV4 * 16)    // 15360
#define STAGE_BYTES  (STAGE_V4 * 16) // 30720
#define NSTAGES 2
#define NTILES  (NCELLS / TILE_C)  // 6272 exact
#define GRID    456                // 152 SMs * 3 blocks
#define SMEM_BYTES (NSTAGES * STAGE_BYTES)  // 61440

__device__ float    g_partial[2048];
__device__ unsigned g_count = 0;

// ---------- PTX helpers ----------
__device__ __forceinline__ uint32_t smem_u32(const void* p) {
    return (uint32_t)__cvta_generic_to_shared(p);
}
__device__ __forceinline__ void mbar_init(uint32_t mbar, uint32_t count) {
    asm volatile("mbarrier.init.shared.b64 [%0], %1;" :: "r"(mbar), "r"(count) : "memory");
}
__device__ __forceinline__ void mbar_expect_tx(uint32_t mbar, uint32_t bytes) {
    asm volatile("mbarrier.arrive.expect_tx.shared.b64 _, [%0], %1;"
                 :: "r"(mbar), "r"(bytes) : "memory");
}
__device__ __forceinline__ void mbar_wait_acq(uint32_t mbar, uint32_t phase) {
    asm volatile(
        "{\n\t.reg .pred P;\n\t"
        "WAIT_%=:\n\t"
        "mbarrier.try_wait.parity.acquire.cta.shared::cta.b64 P, [%0], %1, 0x989680;\n\t"
        "@P bra.uni DONE_%=;\n\t"
        "bra.uni WAIT_%=;\n\t"
        "DONE_%=:\n\t}"
        :: "r"(mbar), "r"(phase) : "memory");
}
__device__ __forceinline__ void tma_bulk_g2s(uint32_t dst, const void* src,
                                             uint32_t bytes, uint32_t mbar) {
    asm volatile("cp.async.bulk.shared::cta.global.mbarrier::complete_tx::bytes "
                 "[%0], [%1], %2, [%3];"
                 :: "r"(dst), "l"(src), "r"(bytes), "r"(mbar) : "memory");
}
__device__ __forceinline__ void fence_async_shared() {
    asm volatile("fence.proxy.async.shared::cta;" ::: "memory");
}

// ---------- math ----------
__device__ __forceinline__ float iou_f(float x1, float y1, float w1, float h1,
                                       float x2, float y2, float w2, float h2) {
    float xl = fmaxf(x1 - w1 * 0.5f, x2 - w2 * 0.5f);
    float yt = fmaxf(y1 - h1 * 0.5f, y2 - h2 * 0.5f);
    float xr = fminf(x1 + w1 * 0.5f, x2 + w2 * 0.5f);
    float yb = fminf(y1 + h1 * 0.5f, y2 + h2 * 0.5f);
    bool valid = (xr >= xl) && (yb >= yt);
    float inter = (xr - xl) * (yb - yt);
    float uni = w1 * h1 + w2 * h2 - inter;
    float safe = (uni == 0.0f) ? 1.0f : uni;
    return valid ? (inter / safe) : 0.0f;
}

__device__ __forceinline__ float cell_loss(float t0, float t1, float t2, float t3, float t4,
                                           float p0, float p1, float p2, float p3, float p4,
                                           float p5, float p6, float p7, float p8, float p9,
                                           float cls) {
    float obj   = (t4 > 0.0f)  ? 1.0f : 0.0f;
    float noobj = (t4 == 0.0f) ? 1.0f : 0.0f;

    float dno = t4 - p4;
    float conf_noobj = noobj * dno * dno;

    float iou1 = iou_f(t0, t1, t2, t3, p0, p1, p2, p3);
    float iou2 = iou_f(t0, t1, t2, t3, p5, p6, p7, p8);
    float resp1 = (iou1 > iou2) ? 1.0f : 0.0f;
    float m1 = obj * resp1;
    float m2 = obj * (1.0f - resp1);

    float d1 = iou1 - p4;
    float d2 = iou2 - p9;
    float conf_obj = m1 * d1 * d1 + m2 * d2 * d2;

    float dx1 = t0 - p0, dy1 = t1 - p1;
    float dx2 = t0 - p5, dy2 = t1 - p6;
    float xy = m1 * (dx1 * dx1 + dy1 * dy1) + m2 * (dx2 * dx2 + dy2 * dy2);

    float dw1 = t2 - p2, dh1 = t3 - p3;
    float dw2 = t2 - p7, dh2 = t3 - p8;
    float wh = m1 * (dw1 * dw1 + dh1 * dh1) + m2 * (dw2 * dw2 + dh2 * dh2);

    return 5.0f * (xy + wh) + conf_obj + 0.5f * conf_noobj + obj * cls;
}

// Even cell of a pair (slots 0..7): static mapping.
__device__ __forceinline__ float even_cell(const float4* __restrict__ SP,
                                           const float4* __restrict__ ST) {
    float cls = 0.0f;
#pragma unroll
    for (int j = 3; j <= 6; j++) {
        float4 a = ST[j], b = SP[j];
        float d0 = a.x - b.x, d1 = a.y - b.y, d2 = a.z - b.z, d3 = a.w - b.w;
        cls += d0 * d0 + d1 * d1 + d2 * d2 + d3 * d3;
    }
    float4 P2 = SP[2], T2 = ST[2];
    { float d0 = T2.z - P2.z, d1 = T2.w - P2.w; cls += d0 * d0 + d1 * d1; }
    float4 P7 = SP[7], T7 = ST[7];
    { float d0 = T7.x - P7.x, d1 = T7.y - P7.y; cls += d0 * d0 + d1 * d1; }

    float4 P0 = SP[0], P1 = SP[1], T0 = ST[0], T1 = ST[1];
    return cell_loss(T0.x, T0.y, T0.z, T0.w, T1.x,
                     P0.x, P0.y, P0.z, P0.w, P1.x,
                     P1.y, P1.z, P1.w, P2.x, P2.y, cls);
}

// Odd cell of a pair (slots 7..14): static mapping.
__device__ __forceinline__ float odd_cell(const float4* __restrict__ SP,
                                          const float4* __restrict__ ST) {
    float cls = 0.0f;
#pragma unroll
    for (int j = 10; j <= 14; j++) {
        float4 a = ST[j], b = SP[j];
        float d0 = a.x - b.x, d1 = a.y - b.y, d2 = a.z - b.z, d3 = a.w - b.w;
        cls += d0 * d0 + d1 * d1 + d2 * d2 + d3 * d3;
    }
    float4 P7 = SP[7], P8 = SP[8], P9 = SP[9];
    float4 T7 = ST[7], T8 = ST[8];
    return cell_loss(T7.z, T7.w, T8.x, T8.y, T8.z,
                     P7.z, P7.w, P8.x, P8.y, P8.z,
                     P8.w, P9.x, P9.y, P9.z, P9.w, cls);
}

__global__ void __launch_bounds__(THREADS)
yolo_fused_kernel(const float* __restrict__ pred,
                  const float* __restrict__ tgt,
                  float* __restrict__ out) {
    extern __shared__ float4 sbuf[];       // 2 stages x 1920 float4
    __shared__ uint64_t mb_full[NSTAGES];
    __shared__ float    swarp[THREADS / 32];
    __shared__ int      s_isLast;

    const int tid  = threadIdx.x;
    const int lane = tid & 31;
    const int wid  = tid >> 5;
    const char* gpb = reinterpret_cast<const char*>(pred);
    const char* gtb = reinterpret_cast<const char*>(tgt);

    uint32_t full_a[NSTAGES], stage_a[NSTAGES];
#pragma unroll
    for (int s = 0; s < NSTAGES; s++) {
        full_a[s]  = smem_u32(&mb_full[s]);
        stage_a[s] = smem_u32(sbuf + s * STAGE_V4);
    }

    if (tid == 0) {
        mbar_init(full_a[0], 1);
        mbar_init(full_a[1], 1);
        fence_async_shared();
    }
    __syncthreads();

    float loss = 0.0f;
    const int pair = ((wid >> 1) << 5) + lane;   // 0..63
    const int odd  = wid & 1;

    int t = blockIdx.x;
    int stage = 0;
    uint32_t ph[NSTAGES] = {0, 0};

    // prologue: fill stage 0 for tile t
    if (tid == 0 && t < NTILES) {
        mbar_expect_tx(full_a[0], STAGE_BYTES);
        tma_bulk_g2s(stage_a[0], gpb + (long)t * TENSOR_BYTES, TENSOR_BYTES, full_a[0]);
        tma_bulk_g2s(stage_a[0] + TENSOR_BYTES, gtb + (long)t * TENSOR_BYTES,
                     TENSOR_BYTES, full_a[0]);
    }

    while (t < NTILES) {
        int tn = t + GRID;
        // refill the other stage for the next tile (its readers finished at
        // the trailing __syncthreads of the previous iteration)
        if (tid == 0 && tn < NTILES) {
            int so = stage ^ 1;
            mbar_expect_tx(full_a[so], STAGE_BYTES);
            tma_bulk_g2s(stage_a[so], gpb + (long)tn * TENSOR_BYTES,
                         TENSOR_BYTES, full_a[so]);
            tma_bulk_g2s(stage_a[so] + TENSOR_BYTES, gtb + (long)tn * TENSOR_BYTES,
                         TENSOR_BYTES, full_a[so]);
        }

        // consume current stage
        mbar_wait_acq(full_a[stage], ph[stage]);
        ph[stage] ^= 1;
        {
            const float4* SP = sbuf + stage * STAGE_V4 + pair * 15;
            const float4* ST = SP + TV4;
            loss += odd ? odd_cell(SP, ST) : even_cell(SP, ST);
        }
        __syncthreads();             // all reads done before this stage refills
        stage ^= 1;
        t = tn;
    }

    // ---- block reduce (deterministic) ----
#pragma unroll
    for (int off = 16; off > 0; off >>= 1)
        loss += __shfl_down_sync(0xFFFFFFFFu, loss, off);

    if (lane == 0) swarp[wid] = loss;
    __syncthreads();

    if (tid == 0) {
        g_partial[blockIdx.x] = swarp[0] + swarp[1] + swarp[2] + swarp[3];
        __threadfence();
        unsigned v = atomicAdd(&g_count, 1u);
        s_isLast = (v == (unsigned)(gridDim.x - 1)) ? 1 : 0;
    }
    __syncthreads();

    // ---- last block: deterministic final reduction ----
    if (s_isLast) {
        __shared__ double sd[THREADS];
        double acc = 0.0;
        for (int i = tid; i < GRID; i += THREADS)
            acc += (double)g_partial[i];
        sd[tid] = acc;
        __syncthreads();
#pragma unroll
        for (int stride = THREADS / 2; stride > 0; stride >>= 1) {
            if (tid < stride) sd[tid] += sd[tid + stride];
            __syncthreads();
        }
        if (tid == 0) {
            out[0] = (float)(sd[0] / 16384.0);
            g_count = 0;   // reset for next graph replay
        }
    }
}

extern "C" void kernel_launch(void* const* d_in, const int* in_sizes, int n_in,
                              void* d_out, int out_size) {
    const float* y  = (const float*)d_in[0];
    const float* gt = (const float*)d_in[1];
    float* out = (float*)d_out;

    static int attr_done = 0;
    if (!attr_done) {
        cudaFuncSetAttribute(yolo_fused_kernel,
                             cudaFuncAttributeMaxDynamicSharedMemorySize, SMEM_BYTES);
        attr_done = 1;
    }

    yolo_fused_kernel<<<GRID, THREADS, SMEM_BYTES>>>(y, gt, out);
}